// round 7
// baseline (speedup 1.0000x reference)
#include <cuda_runtime.h>
#include <cstdint>
#include <math.h>

// Problem constants
#define BB     65536
#define HH     256
#define G4     1024
#define NCOMP  15
#define VV     26
#define EE     64

// ---------------------------------------------------------------------------
// Scratch (device globals; no cudaMalloc allowed)
// ---------------------------------------------------------------------------
__device__ float g_h[BB * HH];                 //  64 MB  h state
__device__ float g_c[BB * HH];                 //  64 MB  c state
__device__ float g_pre[(size_t)BB * G4];       // 256 MB  context@Wi_c + bh
__device__ float g_emb2[27 * G4];              // rows 0..25: embed@Wi_e, row 26: start@Wi_e
__device__ int   g_tok[BB];                    // previous token per row (26 = start)

// ---------------------------------------------------------------------------
// threefry2x32 (matches jax._src.prng exactly)
// ---------------------------------------------------------------------------
__device__ __forceinline__ uint32_t rotl32(uint32_t v, int s) {
    return (v << s) | (v >> (32 - s));
}

__device__ __forceinline__ void tf2x32(uint32_t k0, uint32_t k1,
                                       uint32_t x0, uint32_t x1,
                                       uint32_t& o0, uint32_t& o1) {
    uint32_t k2 = k0 ^ k1 ^ 0x1BD11BDAu;
    uint32_t x = x0 + k0, y = x1 + k1;
    x += y; y = rotl32(y, 13); y ^= x;  x += y; y = rotl32(y, 15); y ^= x;
    x += y; y = rotl32(y, 26); y ^= x;  x += y; y = rotl32(y, 6);  y ^= x;
    x += k1; y += k2 + 1u;
    x += y; y = rotl32(y, 17); y ^= x;  x += y; y = rotl32(y, 29); y ^= x;
    x += y; y = rotl32(y, 16); y ^= x;  x += y; y = rotl32(y, 24); y ^= x;
    x += k2; y += k0 + 2u;
    x += y; y = rotl32(y, 13); y ^= x;  x += y; y = rotl32(y, 15); y ^= x;
    x += y; y = rotl32(y, 26); y ^= x;  x += y; y = rotl32(y, 6);  y ^= x;
    x += k0; y += k1 + 3u;
    x += y; y = rotl32(y, 17); y ^= x;  x += y; y = rotl32(y, 29); y ^= x;
    x += y; y = rotl32(y, 16); y ^= x;  x += y; y = rotl32(y, 24); y ^= x;
    x += k1; y += k2 + 4u;
    x += y; y = rotl32(y, 13); y ^= x;  x += y; y = rotl32(y, 15); y ^= x;
    x += y; y = rotl32(y, 26); y ^= x;  x += y; y = rotl32(y, 6);  y ^= x;
    x += k2; y += k0 + 5u;
    o0 = x; o1 = y;
}

__device__ __forceinline__ float sigm(float x) { return 1.0f / (1.0f + expf(-x)); }

// ---------------------------------------------------------------------------
// Emb2[27,1024]: rows 0..25 = embed_table @ Wi[256:320,:], row 26 = start_embed @ Wi_e
// ---------------------------------------------------------------------------
__global__ void k_emb(const float* __restrict__ emb,
                      const float* __restrict__ start,
                      const float* __restrict__ Wi) {
    __shared__ float s[EE];
    int r = blockIdx.x;          // 0..26
    int tid = threadIdx.x;       // 256
    if (tid < EE) s[tid] = (r < VV) ? emb[r * EE + tid] : start[tid];
    __syncthreads();
    float a0 = 0.f, a1 = 0.f, a2 = 0.f, a3 = 0.f;
    #pragma unroll 8
    for (int e = 0; e < EE; e++) {
        float x = s[e];
        const float* wr = Wi + (size_t)(HH + e) * G4;
        a0 = fmaf(x, wr[tid],       a0);
        a1 = fmaf(x, wr[tid + 256], a1);
        a2 = fmaf(x, wr[tid + 512], a2);
        a3 = fmaf(x, wr[tid + 768], a3);
    }
    g_emb2[r * G4 + tid]       = a0;
    g_emb2[r * G4 + tid + 256] = a1;
    g_emb2[r * G4 + tid + 512] = a2;
    g_emb2[r * G4 + tid + 768] = a3;
}

// ---------------------------------------------------------------------------
// init: h0 = tanh(context@Wp + bp), c0 = 0, tok = 26 (start row of Emb2)
// CTA = 32 rows x 256 cols, 256 threads (thread: 1 col x 32 rows)
// ---------------------------------------------------------------------------
__global__ __launch_bounds__(256)
void k_init(const float* __restrict__ ctx,
            const float* __restrict__ Wp,
            const float* __restrict__ bp) {
    __shared__ float sh[32 * 256];
    int tid = threadIdx.x;
    int row0 = blockIdx.x * 32;

    const float4* src = (const float4*)(ctx + (size_t)row0 * HH);
    float4* dst = (float4*)sh;
    #pragma unroll
    for (int i = 0; i < 8; i++) dst[tid + i * 256] = src[tid + i * 256];
    __syncthreads();

    float acc[32];
    float b = bp[tid];
    #pragma unroll
    for (int r = 0; r < 32; r++) acc[r] = b;

    #pragma unroll 1
    for (int k = 0; k < 256; k += 4) {
        float w[4];
        #pragma unroll
        for (int kk = 0; kk < 4; kk++) w[kk] = Wp[(k + kk) * 256 + tid];
        #pragma unroll
        for (int r = 0; r < 32; r++) {
            float4 hv = *(const float4*)(sh + r * 256 + k);
            acc[r] = fmaf(hv.x, w[0], acc[r]);
            acc[r] = fmaf(hv.y, w[1], acc[r]);
            acc[r] = fmaf(hv.z, w[2], acc[r]);
            acc[r] = fmaf(hv.w, w[3], acc[r]);
        }
    }
    #pragma unroll
    for (int r = 0; r < 32; r++) {
        int row = row0 + r;
        g_h[(size_t)row * HH + tid] = tanhf(acc[r]);
        g_c[(size_t)row * HH + tid] = 0.0f;
    }
    if (tid < 32) g_tok[row0 + tid] = 26;
}

// ---------------------------------------------------------------------------
// pre = context @ Wi[0:256,:] + bh     (B x 1024)
// grid (B/32, 4), CTA = 32 rows x 256 cols
// ---------------------------------------------------------------------------
__global__ __launch_bounds__(256)
void k_pre(const float* __restrict__ ctx,
           const float* __restrict__ Wi,
           const float* __restrict__ bh) {
    __shared__ float sh[32 * 256];
    int tid = threadIdx.x;
    int row0 = blockIdx.x * 32;
    int col = blockIdx.y * 256 + tid;

    const float4* src = (const float4*)(ctx + (size_t)row0 * HH);
    float4* dst = (float4*)sh;
    #pragma unroll
    for (int i = 0; i < 8; i++) dst[tid + i * 256] = src[tid + i * 256];
    __syncthreads();

    float acc[32];
    float b = bh[col];
    #pragma unroll
    for (int r = 0; r < 32; r++) acc[r] = b;

    #pragma unroll 1
    for (int k = 0; k < 256; k += 4) {
        float w[4];
        #pragma unroll
        for (int kk = 0; kk < 4; kk++) w[kk] = Wi[(size_t)(k + kk) * G4 + col];
        #pragma unroll
        for (int r = 0; r < 32; r++) {
            float4 hv = *(const float4*)(sh + r * 256 + k);
            acc[r] = fmaf(hv.x, w[0], acc[r]);
            acc[r] = fmaf(hv.y, w[1], acc[r]);
            acc[r] = fmaf(hv.z, w[2], acc[r]);
            acc[r] = fmaf(hv.w, w[3], acc[r]);
        }
    }
    #pragma unroll
    for (int r = 0; r < 32; r++)
        g_pre[(size_t)(row0 + r) * G4 + col] = acc[r];
}

// ---------------------------------------------------------------------------
// One decode step, fully fused:
//   gates = pre + Emb2[tok_prev] + h@Wh -> LSTM -> h,c -> logits -> sample
// CTA = 32 rows x 1024 gate-cols, 512 threads:
//   tid = (half<<8)|j : j in [0,256) gate column group, half selects 16 rows.
//   Thread accumulates 16 rows x 4 gates (i,f,g,o at j, j+256, j+512, j+768).
// ---------------------------------------------------------------------------
__global__ __launch_bounds__(512)
void k_step(const float* __restrict__ Wh,     // (256,1024)
            const float* __restrict__ Wo,     // (256,26)
            const float* __restrict__ bo,     // (26)
            const int*   __restrict__ seedp,
            float* __restrict__ out_logits,   // (B, NC, V)
            float* __restrict__ out_samples,  // (B, NC) as float, or null
            int step) {
    __shared__ float sh_h[32 * 256];      // h_prev during GEMM, then h_new
    __shared__ float sh_logit[32 * 32];   // padded stride 32
    __shared__ int   sh_tok[32];

    int tid  = threadIdx.x;
    int j    = tid & 255;
    int half = tid >> 8;                  // 0 or 1
    int row0 = blockIdx.x * 32;

    // load h tile (32x256) and previous tokens
    {
        const float4* src = (const float4*)(g_h + (size_t)row0 * HH);
        float4* dst = (float4*)sh_h;
        #pragma unroll
        for (int i = 0; i < 4; i++) dst[tid + i * 512] = src[tid + i * 512];
        if (tid < 32) sh_tok[tid] = g_tok[row0 + tid];
    }
    __syncthreads();

    // accumulators init: pre + Emb2[tok_prev]
    float acc[16][4];
    #pragma unroll
    for (int r = 0; r < 16; r++) {
        int rl = half * 16 + r;
        const float* prer = g_pre + (size_t)(row0 + rl) * G4;
        const float* embr = g_emb2 + sh_tok[rl] * G4;
        #pragma unroll
        for (int gg = 0; gg < 4; gg++)
            acc[r][gg] = prer[gg * 256 + j] + embr[gg * 256 + j];
    }

    // main GEMM: += h @ Wh
    const float* hrow = sh_h + half * 16 * 256;
    #pragma unroll 1
    for (int k = 0; k < 256; k += 4) {
        float w[4][4];
        #pragma unroll
        for (int kk = 0; kk < 4; kk++) {
            const float* wr = Wh + (size_t)(k + kk) * G4 + j;
            w[kk][0] = wr[0];
            w[kk][1] = wr[256];
            w[kk][2] = wr[512];
            w[kk][3] = wr[768];
        }
        #pragma unroll
        for (int r = 0; r < 16; r++) {
            float4 hv = *(const float4*)(hrow + r * 256 + k);
            #pragma unroll
            for (int gg = 0; gg < 4; gg++) {
                acc[r][gg] = fmaf(hv.x, w[0][gg], acc[r][gg]);
                acc[r][gg] = fmaf(hv.y, w[1][gg], acc[r][gg]);
                acc[r][gg] = fmaf(hv.z, w[2][gg], acc[r][gg]);
                acc[r][gg] = fmaf(hv.w, w[3][gg], acc[r][gg]);
            }
        }
    }
    __syncthreads();   // done reading h_prev

    // LSTM elementwise, write h_new / c_new
    #pragma unroll
    for (int r = 0; r < 16; r++) {
        int rl  = half * 16 + r;
        size_t gi = (size_t)(row0 + rl) * HH + j;
        float iv = acc[r][0], fv = acc[r][1], gv = acc[r][2], ov = acc[r][3];
        float cn = sigm(fv) * g_c[gi] + sigm(iv) * tanhf(gv);
        float hn = sigm(ov) * tanhf(cn);
        g_c[gi] = cn;
        g_h[gi] = hn;
        sh_h[rl * 256 + j] = hn;
    }
    __syncthreads();

    // logits = h_new @ Wo + bo  (32 rows x 26 cols, K=256)
    for (int t = tid; t < 32 * VV; t += 512) {
        int r = t / VV, v = t - r * VV;
        const float* hr = sh_h + r * 256;
        float s = bo[v];
        #pragma unroll 8
        for (int k = 0; k < 256; k++) s = fmaf(hr[k], Wo[k * VV + v], s);
        sh_logit[r * 32 + v] = s;
        out_logits[(size_t)(row0 + r) * (NCOMP * VV) + step * VV + v] = s;
    }
    __syncthreads();

    // sampling: warp w handles rows 2w and 2w+1; lanes 0..25 = vocab
    {
        int warp = tid >> 5, lane = tid & 31;
        int sv = seedp[0];
        uint32_t kb1 = 0u, kb2 = (uint32_t)sv;
        uint32_t s1, s2;
        tf2x32(kb1, kb2, 0u, (uint32_t)step, s1, s2);   // foldlike split subkey

        #pragma unroll
        for (int rr = 0; rr < 2; rr++) {
            int r = warp * 2 + rr;
            int row = row0 + r;
            float val = -INFINITY;
            int   idx = VV;
            if (lane < VV) {
                uint32_t o1, o2;
                tf2x32(s1, s2, 0u, (uint32_t)(row * VV + lane), o1, o2);
                uint32_t bits = o1 ^ o2;                 // partitionable 32-bit path
                float f = __uint_as_float((bits >> 9) | 0x3f800000u) - 1.0f;
                float u = fmaxf(f, 1.1754944e-38f);      // uniform(tiny, 1)
                float gum = -logf(-logf(u));
                val = sh_logit[r * 32 + lane] + gum;
                idx = lane;
            }
            #pragma unroll
            for (int off = 16; off; off >>= 1) {
                float ov = __shfl_down_sync(0xffffffffu, val, off);
                int   oi = __shfl_down_sync(0xffffffffu, idx, off);
                if (ov > val || (ov == val && oi < idx)) { val = ov; idx = oi; }
            }
            if (lane == 0) {
                g_tok[row] = idx;
                if (out_samples) out_samples[(size_t)row * NCOMP + step] = (float)idx;
            }
        }
    }
}

// ---------------------------------------------------------------------------
// launch
// ---------------------------------------------------------------------------
extern "C" void kernel_launch(void* const* d_in, const int* in_sizes, int n_in,
                              void* d_out, int out_size) {
    const float* ctx   = (const float*)d_in[0];   // (B, 256)
    const float* emb   = (const float*)d_in[1];   // (26, 64)
    const float* start = (const float*)d_in[2];   // (64,)
    const float* Wp    = (const float*)d_in[3];   // (256, 256)
    const float* bp    = (const float*)d_in[4];   // (256,)
    const float* Wi    = (const float*)d_in[5];   // (320, 1024)
    const float* Wh    = (const float*)d_in[6];   // (256, 1024)
    const float* bh    = (const float*)d_in[7];   // (1024,)
    const float* Wo    = (const float*)d_in[8];   // (256, 26)
    const float* bo    = (const float*)d_in[9];   // (26,)
    const int*   seed  = (const int*)d_in[10];    // scalar

    float* out = (float*)d_out;
    const long long logits_elems = (long long)BB * NCOMP * VV;
    float* out_s = ((long long)out_size >= logits_elems + (long long)BB * NCOMP)
                 ? out + logits_elems : nullptr;

    k_emb <<<27, 256>>>(emb, start, Wi);
    k_init<<<BB / 32, 256>>>(ctx, Wp, bp);
    k_pre <<<dim3(BB / 32, 4), 256>>>(ctx, Wi, bh);
    for (int s = 0; s < NCOMP; s++)
        k_step<<<BB / 32, 512>>>(Wh, Wo, bo, seed, out, out_s, s);
}

// round 9
// speedup vs baseline: 1.1102x; 1.1102x over previous
#include <cuda_runtime.h>
#include <cstdint>
#include <math.h>

// Problem constants
#define BB     65536
#define HH     256
#define G4     1024
#define NCOMP  15
#define VV     26
#define EE     64
#define CHK    16            // K-chunk staged per buffer
#define NCHUNK (HH / CHK)    // 16

// ---------------------------------------------------------------------------
// Scratch (device globals; no cudaMalloc allowed)
// ---------------------------------------------------------------------------
__device__ float g_h[BB * HH];                 //  64 MB  h state
__device__ float g_c[BB * HH];                 //  64 MB  c state
__device__ float g_pre[(size_t)BB * G4];       // 256 MB  (permuted cols: j*4+g)
__device__ float g_emb2[27 * G4];              // permuted cols
__device__ int   g_tok[BB];                    // prev token per row (26 = start)
__device__ float g_Wip[320 * G4];              // Wi, cols permuted j*4+g
__device__ float g_Whp[256 * G4];              // Wh, cols permuted
__device__ float g_bhp[G4];                    // bh, permuted

// ---------------------------------------------------------------------------
// threefry2x32 (matches jax._src.prng exactly)
// ---------------------------------------------------------------------------
__device__ __forceinline__ uint32_t rotl32(uint32_t v, int s) {
    return (v << s) | (v >> (32 - s));
}

__device__ __forceinline__ void tf2x32(uint32_t k0, uint32_t k1,
                                       uint32_t x0, uint32_t x1,
                                       uint32_t& o0, uint32_t& o1) {
    uint32_t k2 = k0 ^ k1 ^ 0x1BD11BDAu;
    uint32_t x = x0 + k0, y = x1 + k1;
    x += y; y = rotl32(y, 13); y ^= x;  x += y; y = rotl32(y, 15); y ^= x;
    x += y; y = rotl32(y, 26); y ^= x;  x += y; y = rotl32(y, 6);  y ^= x;
    x += k1; y += k2 + 1u;
    x += y; y = rotl32(y, 17); y ^= x;  x += y; y = rotl32(y, 29); y ^= x;
    x += y; y = rotl32(y, 16); y ^= x;  x += y; y = rotl32(y, 24); y ^= x;
    x += k2; y += k0 + 2u;
    x += y; y = rotl32(y, 13); y ^= x;  x += y; y = rotl32(y, 15); y ^= x;
    x += y; y = rotl32(y, 26); y ^= x;  x += y; y = rotl32(y, 6);  y ^= x;
    x += k0; y += k1 + 3u;
    x += y; y = rotl32(y, 17); y ^= x;  x += y; y = rotl32(y, 29); y ^= x;
    x += y; y = rotl32(y, 16); y ^= x;  x += y; y = rotl32(y, 24); y ^= x;
    x += k1; y += k2 + 4u;
    x += y; y = rotl32(y, 13); y ^= x;  x += y; y = rotl32(y, 15); y ^= x;
    x += y; y = rotl32(y, 26); y ^= x;  x += y; y = rotl32(y, 6);  y ^= x;
    x += k2; y += k0 + 5u;
    o0 = x; o1 = y;
}

__device__ __forceinline__ float sigm(float x) { return 1.0f / (1.0f + expf(-x)); }

// ---------------------------------------------------------------------------
// cp.async helpers
// ---------------------------------------------------------------------------
__device__ __forceinline__ void cpa16(float* sdst, const float* gsrc) {
    unsigned ds = (unsigned)__cvta_generic_to_shared(sdst);
    asm volatile("cp.async.cg.shared.global [%0], [%1], 16;\n" :: "r"(ds), "l"(gsrc));
}
__device__ __forceinline__ void cpa_commit() {
    asm volatile("cp.async.commit_group;\n" ::: "memory");
}
__device__ __forceinline__ void cpa_wait1() {
    asm volatile("cp.async.wait_group 1;\n" ::: "memory");
}

// Stage one K-chunk (CHK x 1024 floats = 64KB) from gsrc into sdst. 512 threads.
__device__ __forceinline__ void stage_chunk(float* sdst, const float* gsrc, int tid) {
    #pragma unroll
    for (int i = 0; i < 8; i++) {
        int idx = i * 512 + tid;                  // float4 index, 0..4095
        cpa16(sdst + idx * 4, gsrc + idx * 4);
    }
}

// ---------------------------------------------------------------------------
// k_perm: build gate-interleaved weights: Wp[k][j*4+g] = W[k][g*256+j]
// grid 320 x 256
// ---------------------------------------------------------------------------
__global__ void k_perm(const float* __restrict__ Wi,
                       const float* __restrict__ Wh,
                       const float* __restrict__ bh) {
    int k = blockIdx.x, j = threadIdx.x;
    float4 v;
    v.x = Wi[(size_t)k * G4 + j];
    v.y = Wi[(size_t)k * G4 + 256 + j];
    v.z = Wi[(size_t)k * G4 + 512 + j];
    v.w = Wi[(size_t)k * G4 + 768 + j];
    *(float4*)(g_Wip + (size_t)k * G4 + 4 * j) = v;
    if (k < 256) {
        float4 w;
        w.x = Wh[(size_t)k * G4 + j];
        w.y = Wh[(size_t)k * G4 + 256 + j];
        w.z = Wh[(size_t)k * G4 + 512 + j];
        w.w = Wh[(size_t)k * G4 + 768 + j];
        *(float4*)(g_Whp + (size_t)k * G4 + 4 * j) = w;
    }
    if (k == 0) {
        float4 b;
        b.x = bh[j]; b.y = bh[256 + j]; b.z = bh[512 + j]; b.w = bh[768 + j];
        *(float4*)(g_bhp + 4 * j) = b;
    }
}

// ---------------------------------------------------------------------------
// Emb2[27,1024] (permuted cols): rows 0..25 = embed @ Wi_e, row 26 = start @ Wi_e
// ---------------------------------------------------------------------------
__global__ void k_emb(const float* __restrict__ emb,
                      const float* __restrict__ start) {
    __shared__ float s[EE];
    int r = blockIdx.x;          // 0..26
    int tid = threadIdx.x;       // 256
    if (tid < EE) s[tid] = (r < VV) ? emb[r * EE + tid] : start[tid];
    __syncthreads();
    float4 a = make_float4(0.f, 0.f, 0.f, 0.f);
    #pragma unroll 8
    for (int e = 0; e < EE; e++) {
        float x = s[e];
        float4 w = *(const float4*)(g_Wip + (size_t)(HH + e) * G4 + 4 * tid);
        a.x = fmaf(x, w.x, a.x); a.y = fmaf(x, w.y, a.y);
        a.z = fmaf(x, w.z, a.z); a.w = fmaf(x, w.w, a.w);
    }
    *(float4*)(g_emb2 + r * G4 + 4 * tid) = a;
}

// ---------------------------------------------------------------------------
// init: h0 = tanh(context@Wp + bp), c0 = 0, tok = 26
// ---------------------------------------------------------------------------
__global__ __launch_bounds__(256)
void k_init(const float* __restrict__ ctx,
            const float* __restrict__ Wp,
            const float* __restrict__ bp) {
    __shared__ float sh[32 * 256];
    int tid = threadIdx.x;
    int row0 = blockIdx.x * 32;

    const float4* src = (const float4*)(ctx + (size_t)row0 * HH);
    float4* dst = (float4*)sh;
    #pragma unroll
    for (int i = 0; i < 8; i++) dst[tid + i * 256] = src[tid + i * 256];
    __syncthreads();

    float acc[32];
    float b = bp[tid];
    #pragma unroll
    for (int r = 0; r < 32; r++) acc[r] = b;

    #pragma unroll 1
    for (int k = 0; k < 256; k += 4) {
        float w[4];
        #pragma unroll
        for (int kk = 0; kk < 4; kk++) w[kk] = Wp[(k + kk) * 256 + tid];
        #pragma unroll
        for (int r = 0; r < 32; r++) {
            float4 hv = *(const float4*)(sh + r * 256 + k);
            acc[r] = fmaf(hv.x, w[0], acc[r]);
            acc[r] = fmaf(hv.y, w[1], acc[r]);
            acc[r] = fmaf(hv.z, w[2], acc[r]);
            acc[r] = fmaf(hv.w, w[3], acc[r]);
        }
    }
    #pragma unroll
    for (int r = 0; r < 32; r++) {
        int row = row0 + r;
        g_h[(size_t)row * HH + tid] = tanhf(acc[r]);
        g_c[(size_t)row * HH + tid] = 0.0f;
    }
    if (tid < 32) g_tok[row0 + tid] = 26;
}

// ---------------------------------------------------------------------------
// k_pre: g_pre = ctx @ Wi_perm[0:256] + bh_perm  (permuted cols), staged GEMM
// 512 threads, 32 rows/CTA. dyn smem: sw[2][16*1024] + sh_x[32*256]
// ---------------------------------------------------------------------------
__global__ __launch_bounds__(512)
void k_pre(const float* __restrict__ ctx) {
    extern __shared__ float sm[];
    float* sw   = sm;            // 32768 floats
    float* sh_x = sm + 32768;    // 8192 floats

    int tid  = threadIdx.x;
    int j    = tid & 255;
    int half = tid >> 8;
    int row0 = blockIdx.x * 32;

    stage_chunk(sw,         g_Wip,              tid); cpa_commit();
    stage_chunk(sw + 16384, g_Wip + CHK * G4,   tid); cpa_commit();

    {
        const float4* src = (const float4*)(ctx + (size_t)row0 * HH);
        float4* dst = (float4*)sh_x;
        #pragma unroll
        for (int i = 0; i < 4; i++) dst[tid + i * 512] = src[tid + i * 512];
    }
    __syncthreads();

    float4 b4 = *(const float4*)(g_bhp + 4 * j);
    float acc[16][4];
    #pragma unroll
    for (int r = 0; r < 16; r++) {
        acc[r][0] = b4.x; acc[r][1] = b4.y; acc[r][2] = b4.z; acc[r][3] = b4.w;
    }

    const float* hbase = sh_x + half * 16 * 256;
    #pragma unroll 1
    for (int ck = 0; ck < NCHUNK; ck++) {
        cpa_wait1();
        __syncthreads();
        const float* wb = sw + (ck & 1) * 16384;
        const float* hrow = hbase + ck * CHK;
        #pragma unroll
        for (int kk = 0; kk < CHK; kk += 4) {
            float4 w0 = *(const float4*)(wb + (kk + 0) * G4 + 4 * j);
            float4 w1 = *(const float4*)(wb + (kk + 1) * G4 + 4 * j);
            float4 w2 = *(const float4*)(wb + (kk + 2) * G4 + 4 * j);
            float4 w3 = *(const float4*)(wb + (kk + 3) * G4 + 4 * j);
            #pragma unroll
            for (int r = 0; r < 16; r++) {
                float4 hv = *(const float4*)(hrow + r * 256 + kk);
                acc[r][0] = fmaf(hv.x, w0.x, acc[r][0]); acc[r][0] = fmaf(hv.y, w1.x, acc[r][0]);
                acc[r][0] = fmaf(hv.z, w2.x, acc[r][0]); acc[r][0] = fmaf(hv.w, w3.x, acc[r][0]);
                acc[r][1] = fmaf(hv.x, w0.y, acc[r][1]); acc[r][1] = fmaf(hv.y, w1.y, acc[r][1]);
                acc[r][1] = fmaf(hv.z, w2.y, acc[r][1]); acc[r][1] = fmaf(hv.w, w3.y, acc[r][1]);
                acc[r][2] = fmaf(hv.x, w0.z, acc[r][2]); acc[r][2] = fmaf(hv.y, w1.z, acc[r][2]);
                acc[r][2] = fmaf(hv.z, w2.z, acc[r][2]); acc[r][2] = fmaf(hv.w, w3.z, acc[r][2]);
                acc[r][3] = fmaf(hv.x, w0.w, acc[r][3]); acc[r][3] = fmaf(hv.y, w1.w, acc[r][3]);
                acc[r][3] = fmaf(hv.z, w2.w, acc[r][3]); acc[r][3] = fmaf(hv.w, w3.w, acc[r][3]);
            }
        }
        __syncthreads();
        if (ck + 2 < NCHUNK)
            stage_chunk(sw + (ck & 1) * 16384, g_Wip + (size_t)(ck + 2) * CHK * G4, tid);
        cpa_commit();
    }

    #pragma unroll
    for (int r = 0; r < 16; r++) {
        int rl = half * 16 + r;
        float4 o = make_float4(acc[r][0], acc[r][1], acc[r][2], acc[r][3]);
        *(float4*)(g_pre + (size_t)(row0 + rl) * G4 + 4 * j) = o;
    }
}

// ---------------------------------------------------------------------------
// One decode step, fully fused, staged Wh:
//   gates = pre + Emb2[tok] + h@Wh -> LSTM -> logits -> sample
// dyn smem: sw[2][16*1024] | sh_h[32*256] | sh_logit[32*32] | sh_tok[32]
// ---------------------------------------------------------------------------
__global__ __launch_bounds__(512)
void k_step(const float* __restrict__ Wo,     // (256,26)
            const float* __restrict__ bo,     // (26)
            const int*   __restrict__ seedp,
            float* __restrict__ out_logits,   // (B, NC, V)
            float* __restrict__ out_samples,  // (B, NC) as float, or null
            int step) {
    extern __shared__ float sm[];
    float* sw       = sm;                 // 32768
    float* sh_h     = sm + 32768;         // 8192
    float* sh_logit = sh_h + 8192;        // 1024
    int*   sh_tok   = (int*)(sh_logit + 1024);

    int tid  = threadIdx.x;
    int j    = tid & 255;
    int half = tid >> 8;
    int row0 = blockIdx.x * 32;

    stage_chunk(sw,         g_Whp,            tid); cpa_commit();
    stage_chunk(sw + 16384, g_Whp + CHK * G4, tid); cpa_commit();

    // load h tile (32x256) and previous tokens
    {
        const float4* src = (const float4*)(g_h + (size_t)row0 * HH);
        float4* dst = (float4*)sh_h;
        #pragma unroll
        for (int i = 0; i < 4; i++) dst[tid + i * 512] = src[tid + i * 512];
        if (tid < 32) sh_tok[tid] = g_tok[row0 + tid];
    }
    __syncthreads();

    // acc init: pre + Emb2[tok]  (both permuted: float4 per row)
    float acc[16][4];
    #pragma unroll
    for (int r = 0; r < 16; r++) {
        int rl = half * 16 + r;
        float4 p = *(const float4*)(g_pre + (size_t)(row0 + rl) * G4 + 4 * j);
        float4 e = *(const float4*)(g_emb2 + sh_tok[rl] * G4 + 4 * j);
        acc[r][0] = p.x + e.x; acc[r][1] = p.y + e.y;
        acc[r][2] = p.z + e.z; acc[r][3] = p.w + e.w;
    }

    const float* hbase = sh_h + half * 16 * 256;
    #pragma unroll 1
    for (int ck = 0; ck < NCHUNK; ck++) {
        cpa_wait1();
        __syncthreads();
        const float* wb = sw + (ck & 1) * 16384;
        const float* hrow = hbase + ck * CHK;
        #pragma unroll
        for (int kk = 0; kk < CHK; kk += 4) {
            float4 w0 = *(const float4*)(wb + (kk + 0) * G4 + 4 * j);
            float4 w1 = *(const float4*)(wb + (kk + 1) * G4 + 4 * j);
            float4 w2 = *(const float4*)(wb + (kk + 2) * G4 + 4 * j);
            float4 w3 = *(const float4*)(wb + (kk + 3) * G4 + 4 * j);
            #pragma unroll
            for (int r = 0; r < 16; r++) {
                float4 hv = *(const float4*)(hrow + r * 256 + kk);
                acc[r][0] = fmaf(hv.x, w0.x, acc[r][0]); acc[r][0] = fmaf(hv.y, w1.x, acc[r][0]);
                acc[r][0] = fmaf(hv.z, w2.x, acc[r][0]); acc[r][0] = fmaf(hv.w, w3.x, acc[r][0]);
                acc[r][1] = fmaf(hv.x, w0.y, acc[r][1]); acc[r][1] = fmaf(hv.y, w1.y, acc[r][1]);
                acc[r][1] = fmaf(hv.z, w2.y, acc[r][1]); acc[r][1] = fmaf(hv.w, w3.y, acc[r][1]);
                acc[r][2] = fmaf(hv.x, w0.z, acc[r][2]); acc[r][2] = fmaf(hv.y, w1.z, acc[r][2]);
                acc[r][2] = fmaf(hv.z, w2.z, acc[r][2]); acc[r][2] = fmaf(hv.w, w3.z, acc[r][2]);
                acc[r][3] = fmaf(hv.x, w0.w, acc[r][3]); acc[r][3] = fmaf(hv.y, w1.w, acc[r][3]);
                acc[r][3] = fmaf(hv.z, w2.w, acc[r][3]); acc[r][3] = fmaf(hv.w, w3.w, acc[r][3]);
            }
        }
        __syncthreads();
        if (ck + 2 < NCHUNK)
            stage_chunk(sw + (ck & 1) * 16384, g_Whp + (size_t)(ck + 2) * CHK * G4, tid);
        cpa_commit();
    }

    // LSTM elementwise; acc[r][g] = gate g (i,f,g,o) at hidden index j
    #pragma unroll
    for (int r = 0; r < 16; r++) {
        int rl = half * 16 + r;
        size_t gi = (size_t)(row0 + rl) * HH + j;
        float iv = acc[r][0], fv = acc[r][1], gv = acc[r][2], ov = acc[r][3];
        float cn = sigm(fv) * g_c[gi] + sigm(iv) * tanhf(gv);
        float hn = sigm(ov) * tanhf(cn);
        g_c[gi] = cn;
        g_h[gi] = hn;
        sh_h[rl * 256 + j] = hn;
    }
    __syncthreads();

    // stage Wo (256x26 floats) into sw (buffer space now free)
    for (int t = tid; t < 256 * VV; t += 512) sw[t] = Wo[t];
    __syncthreads();

    // logits = h_new @ Wo + bo
    for (int t = tid; t < 32 * VV; t += 512) {
        int r = t / VV, v = t - r * VV;
        const float* hr = sh_h + r * 256;
        float s = bo[v];
        #pragma unroll 8
        for (int k = 0; k < 256; k++) s = fmaf(hr[k], sw[k * VV + v], s);
        sh_logit[r * 32 + v] = s;
        out_logits[(size_t)(row0 + r) * (NCOMP * VV) + step * VV + v] = s;
    }
    __syncthreads();

    // sampling: warp w handles rows 2w, 2w+1; lanes 0..25 = vocab (exact jax path)
    {
        int warp = tid >> 5, lane = tid & 31;
        int sv = seedp[0];
        uint32_t s1, s2;
        tf2x32(0u, (uint32_t)sv, 0u, (uint32_t)step, s1, s2);

        #pragma unroll
        for (int rr = 0; rr < 2; rr++) {
            int r = warp * 2 + rr;
            int row = row0 + r;
            float val = -INFINITY;
            int   idx = VV;
            if (lane < VV) {
                uint32_t o1, o2;
                tf2x32(s1, s2, 0u, (uint32_t)(row * VV + lane), o1, o2);
                uint32_t bits = o1 ^ o2;
                float f = __uint_as_float((bits >> 9) | 0x3f800000u) - 1.0f;
                float u = fmaxf(f, 1.1754944e-38f);
                float gum = -logf(-logf(u));
                val = sh_logit[r * 32 + lane] + gum;
                idx = lane;
            }
            #pragma unroll
            for (int off = 16; off; off >>= 1) {
                float ov = __shfl_down_sync(0xffffffffu, val, off);
                int   oi = __shfl_down_sync(0xffffffffu, idx, off);
                if (ov > val || (ov == val && oi < idx)) { val = ov; idx = oi; }
            }
            if (lane == 0) {
                g_tok[row] = idx;
                if (out_samples) out_samples[(size_t)row * NCOMP + step] = (float)idx;
            }
        }
    }
}

// ---------------------------------------------------------------------------
// launch
// ---------------------------------------------------------------------------
extern "C" void kernel_launch(void* const* d_in, const int* in_sizes, int n_in,
                              void* d_out, int out_size) {
    const float* ctx   = (const float*)d_in[0];
    const float* emb   = (const float*)d_in[1];
    const float* start = (const float*)d_in[2];
    const float* Wp    = (const float*)d_in[3];
    const float* bp    = (const float*)d_in[4];
    const float* Wi    = (const float*)d_in[5];
    const float* Wh    = (const float*)d_in[6];
    const float* bh    = (const float*)d_in[7];
    const float* Wo    = (const float*)d_in[8];
    const float* bo    = (const float*)d_in[9];
    const int*   seed  = (const int*)d_in[10];

    float* out = (float*)d_out;
    const long long logits_elems = (long long)BB * NCOMP * VV;
    float* out_s = ((long long)out_size >= logits_elems + (long long)BB * NCOMP)
                 ? out + logits_elems : nullptr;

    const int SMEM_STEP = (32768 + 8192 + 1024) * 4 + 128;   // 168,064 B
    const int SMEM_PRE  = (32768 + 8192) * 4;                // 163,840 B
    cudaFuncSetAttribute(k_step, cudaFuncAttributeMaxDynamicSharedMemorySize, SMEM_STEP);
    cudaFuncSetAttribute(k_pre,  cudaFuncAttributeMaxDynamicSharedMemorySize, SMEM_PRE);

    k_perm<<<320, 256>>>(Wi, Wh, bh);
    k_emb <<<27, 256>>>(emb, start);
    k_init<<<BB / 32, 256>>>(ctx, Wp, bp);
    k_pre <<<BB / 32, 512, SMEM_PRE>>>(ctx);
    for (int s = 0; s < NCOMP; s++)
        k_step<<<BB / 32, 512, SMEM_STEP>>>(Wo, bo, seed, out, out_s, s);
}

// round 10
// speedup vs baseline: 1.1983x; 1.0793x over previous
#include <cuda_runtime.h>
#include <cstdint>
#include <math.h>

// Problem constants
#define BB     65536
#define HH     256
#define G4     1024
#define NCOMP  15
#define VV     26
#define EE     64
#define CHK    16            // K-chunk staged per buffer
#define NCHUNK (HH / CHK)    // 16
#define PAD    36            // padded row stride for transposed h tile

// ---------------------------------------------------------------------------
// Scratch (device globals; no cudaMalloc allowed)
// ---------------------------------------------------------------------------
__device__ float g_hT[BB * HH];                //  64 MB  h state, per-32-row-block transposed [blk][k][r]
__device__ float g_c[BB * HH];                 //  64 MB  c state, [row][j]
__device__ float g_pre[(size_t)BB * G4];       // 256 MB  (permuted cols: j*4+g)
__device__ float g_emb2[27 * G4];              // permuted cols
__device__ int   g_tok[BB];                    // prev token per row (26 = start)
__device__ float g_Wip[320 * G4];              // Wi, cols permuted j*4+g
__device__ float g_Whp[256 * G4];              // Wh, cols permuted
__device__ float g_bhp[G4];                    // bh, permuted

// ---------------------------------------------------------------------------
// threefry2x32 (matches jax._src.prng exactly)
// ---------------------------------------------------------------------------
__device__ __forceinline__ uint32_t rotl32(uint32_t v, int s) {
    return (v << s) | (v >> (32 - s));
}

__device__ __forceinline__ void tf2x32(uint32_t k0, uint32_t k1,
                                       uint32_t x0, uint32_t x1,
                                       uint32_t& o0, uint32_t& o1) {
    uint32_t k2 = k0 ^ k1 ^ 0x1BD11BDAu;
    uint32_t x = x0 + k0, y = x1 + k1;
    x += y; y = rotl32(y, 13); y ^= x;  x += y; y = rotl32(y, 15); y ^= x;
    x += y; y = rotl32(y, 26); y ^= x;  x += y; y = rotl32(y, 6);  y ^= x;
    x += k1; y += k2 + 1u;
    x += y; y = rotl32(y, 17); y ^= x;  x += y; y = rotl32(y, 29); y ^= x;
    x += y; y = rotl32(y, 16); y ^= x;  x += y; y = rotl32(y, 24); y ^= x;
    x += k2; y += k0 + 2u;
    x += y; y = rotl32(y, 13); y ^= x;  x += y; y = rotl32(y, 15); y ^= x;
    x += y; y = rotl32(y, 26); y ^= x;  x += y; y = rotl32(y, 6);  y ^= x;
    x += k0; y += k1 + 3u;
    x += y; y = rotl32(y, 17); y ^= x;  x += y; y = rotl32(y, 29); y ^= x;
    x += y; y = rotl32(y, 16); y ^= x;  x += y; y = rotl32(y, 24); y ^= x;
    x += k1; y += k2 + 4u;
    x += y; y = rotl32(y, 13); y ^= x;  x += y; y = rotl32(y, 15); y ^= x;
    x += y; y = rotl32(y, 26); y ^= x;  x += y; y = rotl32(y, 6);  y ^= x;
    x += k2; y += k0 + 5u;
    o0 = x; o1 = y;
}

__device__ __forceinline__ float sigm(float x) { return 1.0f / (1.0f + expf(-x)); }

// ---------------------------------------------------------------------------
// packed f32x2 helpers (SASS FFMA2 — only reachable via PTX fma.rn.f32x2)
// ---------------------------------------------------------------------------
__device__ __forceinline__ void ffma2(uint64_t& d, uint64_t a, uint64_t b) {
    asm("fma.rn.f32x2 %0, %1, %2, %0;" : "+l"(d) : "l"(a), "l"(b));
}
__device__ __forceinline__ uint64_t bcast2(float x) {
    uint64_t o;
    asm("mov.b64 %0, {%1, %1};" : "=l"(o) : "f"(x));
    return o;
}
__device__ __forceinline__ uint64_t pack2(float lo, float hi) {
    uint64_t o;
    asm("mov.b64 %0, {%1, %2};" : "=l"(o) : "f"(lo), "f"(hi));
    return o;
}
__device__ __forceinline__ void unpack2(uint64_t v, float& lo, float& hi) {
    asm("mov.b64 {%0, %1}, %2;" : "=f"(lo), "=f"(hi) : "l"(v));
}

// ---------------------------------------------------------------------------
// cp.async helpers
// ---------------------------------------------------------------------------
__device__ __forceinline__ void cpa16(float* sdst, const float* gsrc) {
    unsigned ds = (unsigned)__cvta_generic_to_shared(sdst);
    asm volatile("cp.async.cg.shared.global [%0], [%1], 16;\n" :: "r"(ds), "l"(gsrc));
}
__device__ __forceinline__ void cpa_commit() {
    asm volatile("cp.async.commit_group;\n" ::: "memory");
}
__device__ __forceinline__ void cpa_wait1() {
    asm volatile("cp.async.wait_group 1;\n" ::: "memory");
}

// Stage one K-chunk (CHK x 1024 floats = 64KB). 512 threads.
__device__ __forceinline__ void stage_chunk(float* sdst, const float* gsrc, int tid) {
    #pragma unroll
    for (int i = 0; i < 8; i++) {
        int idx = i * 512 + tid;
        cpa16(sdst + idx * 4, gsrc + idx * 4);
    }
}

// ---------------------------------------------------------------------------
// Shared inner GEMM core: acc[p][g] (packed row-pairs) += hT-chunk @ w-chunk
// hT: padded transposed activation tile base for this thread's half.
// ---------------------------------------------------------------------------
__device__ __forceinline__ void gemm_chunk(uint64_t acc[8][4],
                                           const float* __restrict__ wb,
                                           const float* __restrict__ hT,
                                           int j) {
    #pragma unroll
    for (int kk = 0; kk < CHK; kk++) {
        float4 w = *(const float4*)(wb + kk * G4 + 4 * j);
        uint64_t wp0 = bcast2(w.x);
        uint64_t wp1 = bcast2(w.y);
        uint64_t wp2 = bcast2(w.z);
        uint64_t wp3 = bcast2(w.w);
        const float* hk = hT + kk * PAD;
        #pragma unroll
        for (int p = 0; p < 8; p++) {
            uint64_t hv = *(const uint64_t*)(hk + 2 * p);   // rows (2p,2p+1), broadcast LDS.64
            ffma2(acc[p][0], hv, wp0);
            ffma2(acc[p][1], hv, wp1);
            ffma2(acc[p][2], hv, wp2);
            ffma2(acc[p][3], hv, wp3);
        }
    }
}

// ---------------------------------------------------------------------------
// k_perm: gate-interleaved weights: Wp[k][j*4+g] = W[k][g*256+j]
// ---------------------------------------------------------------------------
__global__ void k_perm(const float* __restrict__ Wi,
                       const float* __restrict__ Wh,
                       const float* __restrict__ bh) {
    int k = blockIdx.x, j = threadIdx.x;
    float4 v;
    v.x = Wi[(size_t)k * G4 + j];
    v.y = Wi[(size_t)k * G4 + 256 + j];
    v.z = Wi[(size_t)k * G4 + 512 + j];
    v.w = Wi[(size_t)k * G4 + 768 + j];
    *(float4*)(g_Wip + (size_t)k * G4 + 4 * j) = v;
    if (k < 256) {
        float4 w;
        w.x = Wh[(size_t)k * G4 + j];
        w.y = Wh[(size_t)k * G4 + 256 + j];
        w.z = Wh[(size_t)k * G4 + 512 + j];
        w.w = Wh[(size_t)k * G4 + 768 + j];
        *(float4*)(g_Whp + (size_t)k * G4 + 4 * j) = w;
    }
    if (k == 0) {
        float4 b;
        b.x = bh[j]; b.y = bh[256 + j]; b.z = bh[512 + j]; b.w = bh[768 + j];
        *(float4*)(g_bhp + 4 * j) = b;
    }
}

// ---------------------------------------------------------------------------
// Emb2[27,1024] (permuted cols)
// ---------------------------------------------------------------------------
__global__ void k_emb(const float* __restrict__ emb,
                      const float* __restrict__ start) {
    __shared__ float s[EE];
    int r = blockIdx.x;
    int tid = threadIdx.x;
    if (tid < EE) s[tid] = (r < VV) ? emb[r * EE + tid] : start[tid];
    __syncthreads();
    float4 a = make_float4(0.f, 0.f, 0.f, 0.f);
    #pragma unroll 8
    for (int e = 0; e < EE; e++) {
        float x = s[e];
        float4 w = *(const float4*)(g_Wip + (size_t)(HH + e) * G4 + 4 * tid);
        a.x = fmaf(x, w.x, a.x); a.y = fmaf(x, w.y, a.y);
        a.z = fmaf(x, w.z, a.z); a.w = fmaf(x, w.w, a.w);
    }
    *(float4*)(g_emb2 + r * G4 + 4 * tid) = a;
}

// ---------------------------------------------------------------------------
// init: h0 = tanh(context@Wp + bp) -> g_hT transposed; c0 = 0; tok = 26
// ---------------------------------------------------------------------------
__global__ __launch_bounds__(256)
void k_init(const float* __restrict__ ctx,
            const float* __restrict__ Wp,
            const float* __restrict__ bp) {
    __shared__ float sh[32 * 256];
    int tid = threadIdx.x;
    int row0 = blockIdx.x * 32;

    const float4* src = (const float4*)(ctx + (size_t)row0 * HH);
    float4* dst = (float4*)sh;
    #pragma unroll
    for (int i = 0; i < 8; i++) dst[tid + i * 256] = src[tid + i * 256];
    __syncthreads();

    float acc[32];
    float b = bp[tid];
    #pragma unroll
    for (int r = 0; r < 32; r++) acc[r] = b;

    #pragma unroll 1
    for (int k = 0; k < 256; k += 4) {
        float w[4];
        #pragma unroll
        for (int kk = 0; kk < 4; kk++) w[kk] = Wp[(k + kk) * 256 + tid];
        #pragma unroll
        for (int r = 0; r < 32; r++) {
            float4 hv = *(const float4*)(sh + r * 256 + k);
            acc[r] = fmaf(hv.x, w[0], acc[r]);
            acc[r] = fmaf(hv.y, w[1], acc[r]);
            acc[r] = fmaf(hv.z, w[2], acc[r]);
            acc[r] = fmaf(hv.w, w[3], acc[r]);
        }
    }
    // transposed h store: column tid owns 32 contiguous floats [blk][tid][0..31]
    float4* hdst = (float4*)(g_hT + (size_t)blockIdx.x * 8192 + tid * 32);
    #pragma unroll
    for (int q = 0; q < 8; q++)
        hdst[q] = make_float4(tanhf(acc[4 * q]), tanhf(acc[4 * q + 1]),
                              tanhf(acc[4 * q + 2]), tanhf(acc[4 * q + 3]));
    #pragma unroll
    for (int r = 0; r < 32; r++)
        g_c[(size_t)(row0 + r) * HH + tid] = 0.0f;
    if (tid < 32) g_tok[row0 + tid] = 26;
}

// ---------------------------------------------------------------------------
// k_pre: g_pre = ctx @ Wi_perm[0:256] + bh_perm  (packed f32x2 core)
// dyn smem: sw[2][16*1024] | sh_xT[256*PAD]
// ---------------------------------------------------------------------------
__global__ __launch_bounds__(512)
void k_pre(const float* __restrict__ ctx) {
    extern __shared__ float sm[];
    float* sw    = sm;              // 32768 floats
    float* sh_xT = sm + 32768;      // 256*PAD floats

    int tid  = threadIdx.x;
    int j    = tid & 255;
    int half = tid >> 8;
    int row0 = blockIdx.x * 32;

    stage_chunk(sw,         g_Wip,            tid); cpa_commit();
    stage_chunk(sw + 16384, g_Wip + CHK * G4, tid); cpa_commit();

    // transpose-load ctx tile (32 rows x 256) into padded [k][r]
    {
        const float4* src = (const float4*)(ctx + (size_t)row0 * HH);
        #pragma unroll
        for (int i = 0; i < 4; i++) {
            int idx4 = tid + i * 512;          // over 2048 float4s
            int r  = idx4 >> 6;                // row
            int kc = idx4 & 63;                // float4 column
            float4 v = src[idx4];
            sh_xT[(4 * kc + 0) * PAD + r] = v.x;
            sh_xT[(4 * kc + 1) * PAD + r] = v.y;
            sh_xT[(4 * kc + 2) * PAD + r] = v.z;
            sh_xT[(4 * kc + 3) * PAD + r] = v.w;
        }
    }
    __syncthreads();

    float4 b4 = *(const float4*)(g_bhp + 4 * j);
    uint64_t acc[8][4];
    #pragma unroll
    for (int p = 0; p < 8; p++) {
        acc[p][0] = bcast2(b4.x); acc[p][1] = bcast2(b4.y);
        acc[p][2] = bcast2(b4.z); acc[p][3] = bcast2(b4.w);
    }

    const float* hbase = sh_xT + half * 16;
    #pragma unroll 1
    for (int ck = 0; ck < NCHUNK; ck++) {
        cpa_wait1();
        __syncthreads();
        gemm_chunk(acc, sw + (ck & 1) * 16384, hbase + ck * CHK * PAD, j);
        __syncthreads();
        if (ck + 2 < NCHUNK)
            stage_chunk(sw + (ck & 1) * 16384, g_Wip + (size_t)(ck + 2) * CHK * G4, tid);
        cpa_commit();
    }

    #pragma unroll
    for (int p = 0; p < 8; p++) {
        int r0 = half * 16 + 2 * p;
        float a0, a1, b0, b1, c0, c1, d0, d1;
        unpack2(acc[p][0], a0, a1); unpack2(acc[p][1], b0, b1);
        unpack2(acc[p][2], c0, c1); unpack2(acc[p][3], d0, d1);
        *(float4*)(g_pre + (size_t)(row0 + r0) * G4 + 4 * j)     = make_float4(a0, b0, c0, d0);
        *(float4*)(g_pre + (size_t)(row0 + r0 + 1) * G4 + 4 * j) = make_float4(a1, b1, c1, d1);
    }
}

// ---------------------------------------------------------------------------
// One decode step, fully fused, packed f32x2 GEMM:
// dyn smem: sw[2][16*1024] | sh_hT[256*PAD] | sh_logit[32*32] | sh_tok[32]
// ---------------------------------------------------------------------------
__global__ __launch_bounds__(512)
void k_step(const float* __restrict__ Wo,     // (256,26)
            const float* __restrict__ bo,     // (26)
            const int*   __restrict__ seedp,
            float* __restrict__ out_logits,   // (B, NC, V)
            float* __restrict__ out_samples,  // (B, NC) as float, or null
            int step) {
    extern __shared__ float sm[];
    float* sw       = sm;                    // 32768
    float* sh_hT    = sm + 32768;            // 256*PAD = 9216
    float* sh_logit = sh_hT + 256 * PAD;     // 1024
    int*   sh_tok   = (int*)(sh_logit + 1024);

    int tid  = threadIdx.x;
    int j    = tid & 255;
    int half = tid >> 8;
    int row0 = blockIdx.x * 32;

    stage_chunk(sw,         g_Whp,            tid); cpa_commit();
    stage_chunk(sw + 16384, g_Whp + CHK * G4, tid); cpa_commit();

    // load transposed h tile into padded shared; tokens
    {
        const float4* src = (const float4*)(g_hT + (size_t)blockIdx.x * 8192);
        #pragma unroll
        for (int i = 0; i < 4; i++) {
            int idx4 = tid + i * 512;          // 2048 float4s
            int k  = idx4 >> 3;                // 8 float4 per k (32 floats)
            int r4 = (idx4 & 7) * 4;
            *(float4*)(sh_hT + k * PAD + r4) = src[idx4];
        }
        if (tid < 32) sh_tok[tid] = g_tok[row0 + tid];
    }
    __syncthreads();

    // acc init: pre + Emb2[tok], packed across row pairs
    uint64_t acc[8][4];
    #pragma unroll
    for (int p = 0; p < 8; p++) {
        int r0 = half * 16 + 2 * p;
        float4 p0 = *(const float4*)(g_pre + (size_t)(row0 + r0) * G4 + 4 * j);
        float4 e0 = *(const float4*)(g_emb2 + sh_tok[r0] * G4 + 4 * j);
        float4 p1 = *(const float4*)(g_pre + (size_t)(row0 + r0 + 1) * G4 + 4 * j);
        float4 e1 = *(const float4*)(g_emb2 + sh_tok[r0 + 1] * G4 + 4 * j);
        acc[p][0] = pack2(p0.x + e0.x, p1.x + e1.x);
        acc[p][1] = pack2(p0.y + e0.y, p1.y + e1.y);
        acc[p][2] = pack2(p0.z + e0.z, p1.z + e1.z);
        acc[p][3] = pack2(p0.w + e0.w, p1.w + e1.w);
    }

    const float* hbase = sh_hT + half * 16;
    #pragma unroll 1
    for (int ck = 0; ck < NCHUNK; ck++) {
        cpa_wait1();
        __syncthreads();
        gemm_chunk(acc, sw + (ck & 1) * 16384, hbase + ck * CHK * PAD, j);
        __syncthreads();
        if (ck + 2 < NCHUNK)
            stage_chunk(sw + (ck & 1) * 16384, g_Whp + (size_t)(ck + 2) * CHK * G4, tid);
        cpa_commit();
    }

    // LSTM elementwise on unpacked row pairs; write c, h (transposed), sh_hT
    float hn16[16];
    #pragma unroll
    for (int p = 0; p < 8; p++) {
        int r0 = half * 16 + 2 * p;
        float i0, i1, f0, f1, gg0, gg1, o0, o1;
        unpack2(acc[p][0], i0, i1); unpack2(acc[p][1], f0, f1);
        unpack2(acc[p][2], gg0, gg1); unpack2(acc[p][3], o0, o1);
        size_t gi0 = (size_t)(row0 + r0) * HH + j;
        float cn0 = sigm(f0) * g_c[gi0] + sigm(i0) * tanhf(gg0);
        float hn0 = sigm(o0) * tanhf(cn0);
        g_c[gi0] = cn0;
        size_t gi1 = gi0 + HH;
        float cn1 = sigm(f1) * g_c[gi1] + sigm(i1) * tanhf(gg1);
        float hn1 = sigm(o1) * tanhf(cn1);
        g_c[gi1] = cn1;
        sh_hT[j * PAD + r0]     = hn0;
        sh_hT[j * PAD + r0 + 1] = hn1;
        hn16[2 * p] = hn0; hn16[2 * p + 1] = hn1;
    }
    // h_new -> g_hT: 16 contiguous floats per (j, half)
    {
        float4* hdst = (float4*)(g_hT + (size_t)blockIdx.x * 8192 + j * 32 + half * 16);
        #pragma unroll
        for (int q = 0; q < 4; q++)
            hdst[q] = make_float4(hn16[4 * q], hn16[4 * q + 1], hn16[4 * q + 2], hn16[4 * q + 3]);
    }
    __syncthreads();

    // stage Wo into sw (weight buffers now free)
    for (int t = tid; t < 256 * VV; t += 512) sw[t] = Wo[t];
    __syncthreads();

    // logits = h_new @ Wo + bo   (reads transposed sh_hT)
    for (int t = tid; t < 32 * VV; t += 512) {
        int r = t / VV, v = t - r * VV;
        float s = bo[v];
        #pragma unroll 8
        for (int k = 0; k < 256; k++) s = fmaf(sh_hT[k * PAD + r], sw[k * VV + v], s);
        sh_logit[r * 32 + v] = s;
        out_logits[(size_t)(row0 + r) * (NCOMP * VV) + step * VV + v] = s;
    }
    __syncthreads();

    // sampling: warp w handles rows 2w, 2w+1; lanes 0..25 = vocab (exact jax path)
    {
        int warp = tid >> 5, lane = tid & 31;
        int sv = seedp[0];
        uint32_t s1, s2;
        tf2x32(0u, (uint32_t)sv, 0u, (uint32_t)step, s1, s2);

        #pragma unroll
        for (int rr = 0; rr < 2; rr++) {
            int r = warp * 2 + rr;
            int row = row0 + r;
            float val = -INFINITY;
            int   idx = VV;
            if (lane < VV) {
                uint32_t o1, o2;
                tf2x32(s1, s2, 0u, (uint32_t)(row * VV + lane), o1, o2);
                uint32_t bits = o1 ^ o2;
                float f = __uint_as_float((bits >> 9) | 0x3f800000u) - 1.0f;
                float u = fmaxf(f, 1.1754944e-38f);
                float gum = -logf(-logf(u));
                val = sh_logit[r * 32 + lane] + gum;
                idx = lane;
            }
            #pragma unroll
            for (int off = 16; off; off >>= 1) {
                float ov = __shfl_down_sync(0xffffffffu, val, off);
                int   oi = __shfl_down_sync(0xffffffffu, idx, off);
                if (ov > val || (ov == val && oi < idx)) { val = ov; idx = oi; }
            }
            if (lane == 0) {
                g_tok[row] = idx;
                if (out_samples) out_samples[(size_t)row * NCOMP + step] = (float)idx;
            }
        }
    }
}

// ---------------------------------------------------------------------------
// launch
// ---------------------------------------------------------------------------
extern "C" void kernel_launch(void* const* d_in, const int* in_sizes, int n_in,
                              void* d_out, int out_size) {
    const float* ctx   = (const float*)d_in[0];
    const float* emb   = (const float*)d_in[1];
    const float* start = (const float*)d_in[2];
    const float* Wp    = (const float*)d_in[3];
    const float* bp    = (const float*)d_in[4];
    const float* Wi    = (const float*)d_in[5];
    const float* Wh    = (const float*)d_in[6];
    const float* bh    = (const float*)d_in[7];
    const float* Wo    = (const float*)d_in[8];
    const float* bo    = (const float*)d_in[9];
    const int*   seed  = (const int*)d_in[10];

    float* out = (float*)d_out;
    const long long logits_elems = (long long)BB * NCOMP * VV;
    float* out_s = ((long long)out_size >= logits_elems + (long long)BB * NCOMP)
                 ? out + logits_elems : nullptr;

    const int SMEM_STEP = (32768 + 256 * PAD + 1024) * 4 + 256;
    const int SMEM_PRE  = (32768 + 256 * PAD) * 4;
    cudaFuncSetAttribute(k_step, cudaFuncAttributeMaxDynamicSharedMemorySize, SMEM_STEP);
    cudaFuncSetAttribute(k_pre,  cudaFuncAttributeMaxDynamicSharedMemorySize, SMEM_PRE);

    k_perm<<<320, 256>>>(Wi, Wh, bh);
    k_emb <<<27, 256>>>(emb, start);
    k_init<<<BB / 32, 256>>>(ctx, Wp, bp);
    k_pre <<<BB / 32, 512, SMEM_PRE>>>(ctx);
    for (int s = 0; s < NCOMP; s++)
        k_step<<<BB / 32, 512, SMEM_STEP>>>(Wo, bo, seed, out, out_s, s);
}